// round 6
// baseline (speedup 1.0000x reference)
#include <cuda_runtime.h>
#include <math.h>

#define Bb 16
#define II 512
#define HH 1024
#define BH (Bb*HH)            // 16384
#define NKC 6                 // K-chunks of 256 columns

// Output offsets (floats): h, c, e_w_ix, e_w_ih, e_b_i, e_w_fx, e_w_fh, e_b_f, e_w_cx, e_w_ch, e_b_c
#define OFF_H     0
#define OFF_C     16384
#define OFF_EWIX  32768
#define OFF_EWIH  8421376
#define OFF_EBI   25198592
#define OFF_EWFX  25214976
#define OFF_EWFH  33603584
#define OFF_EBF   50380800
#define OFF_EWCX  50397184
#define OFF_EWCH  58785792
#define OFF_EBC   75563008

// Scratch (no allocation allowed)
__device__ float g_part[NKC][4 * BH];   // partial pre-activations per K-chunk

struct GatePtrs {
    const float* wx[4];
    const float* wh[4];
};

#define FMA4(A, Z, ACC)                         \
    ACC = fmaf((A).x, (Z).x, ACC);              \
    ACC = fmaf((A).y, (Z).y, ACC);              \
    ACC = fmaf((A).z, (Z).z, ACC);              \
    ACC = fmaf((A).w, (Z).w, ACC);

// ---------------------------------------------------------------------------
// Kernel 1: gate pre-activation partials.
// grid = (HH/16, 4 gates, 6 K-chunks of 256 cols), block = 256 (8 warps).
// chunks 0-1: x columns; chunks 2-5: h_last columns.
// Each warp: 2 consecutive j-rows x 16 batches (32 accumulators).
// 16KB operand staging -> 3 blocks/SM (24 warps) for latency hiding.
// ---------------------------------------------------------------------------
__global__ __launch_bounds__(256, 3) void gates_kernel(
    const float* __restrict__ x, const float* __restrict__ h_last, GatePtrs p)
{
    __shared__ float4 sz[1024];    // 16 b * 64 float4 = 16KB

    const int tid   = threadIdx.x;
    const int chunk = blockIdx.z;
    const int g     = blockIdx.y;

    // Stage this chunk's operand: sz[b*64 + kq]
    {
        const float4* src;
        int rowf4, off;
        if (chunk < 2) { src = (const float4*)x;      rowf4 = 128; off = chunk * 64; }
        else           { src = (const float4*)h_last; rowf4 = 256; off = (chunk - 2) * 64; }
#pragma unroll
        for (int t = tid; t < 1024; t += 256) {
            int b = t >> 6, kq = t & 63;
            sz[t] = src[b * rowf4 + off + kq];
        }
    }
    __syncthreads();

    const int warp = tid >> 5;
    const int lane = tid & 31;
    const int j0   = blockIdx.x * 16 + warp * 2;

    const float* wbase = (chunk < 2) ? p.wx[g] : p.wh[g];
    const int rowlen   = (chunk < 2) ? II : HH;
    const int koff     = (chunk < 2) ? chunk * 256 : (chunk - 2) * 256;

    const float4* w0 = (const float4*)(wbase + (size_t)j0 * rowlen + koff);
    const float4* w1 = (const float4*)(wbase + (size_t)(j0 + 1) * rowlen + koff);

    // Front-batch weight loads (4 independent LDG.128)
    float4 wr0[2], wr1[2];
#pragma unroll
    for (int it = 0; it < 2; it++) {
        wr0[it] = w0[it * 32 + lane];
        wr1[it] = w1[it * 32 + lane];
    }

    // a[m]: m = jj*16 + b
    float a[32];
#pragma unroll
    for (int m = 0; m < 32; m++) a[m] = 0.f;

#pragma unroll
    for (int it = 0; it < 2; it++) {
        const int k4 = it * 32 + lane;
#pragma unroll
        for (int b = 0; b < Bb; b++) {
            float4 z = sz[b * 64 + k4];
            FMA4(wr0[it], z, a[b]);
            FMA4(wr1[it], z, a[16 + b]);
        }
    }

    // Multi-value butterfly reduction: 5 stages, value count halves each.
#pragma unroll
    for (int k = 0; k < 5; k++) {
        const int d = 1 << k;
        const int n = 32 >> k;
        const bool hi = (lane >> k) & 1;
#pragma unroll
        for (int m = 0; m < 16; m++) {
            if (m < n / 2) {
                float mine = hi ? a[m] : a[m + n / 2];
                float got  = __shfl_xor_sync(0xffffffffu, mine, d);
                a[m] = (hi ? a[m + n / 2] : a[m]) + got;
            }
        }
    }

    // lane holds value index bitrev5(lane)
    const unsigned rev = __brev((unsigned)lane) >> 27;
    const int jj = rev >> 4;
    const int b  = rev & 15;
    g_part[chunk][g * BH + b * HH + j0 + jj] = a[0];
}

// ---------------------------------------------------------------------------
// Kernel 2: fused pointwise + HBM-bound trace update.
// JT=16 -> grid = (64, 16) = 1024 blocks = ONE full wave at 8 blocks/SM.
// sh/sx operand values are hoisted out of the streaming loops (invariant
// per thread); scf index is compile-time after unroll.
// ---------------------------------------------------------------------------
#define JT 16

__global__ __launch_bounds__(256) void trace_kernel(
    const float* __restrict__ x, const float* __restrict__ h_last,
    const float* __restrict__ c_last,
    const float* __restrict__ b_i, const float* __restrict__ b_f,
    const float* __restrict__ b_o, const float* __restrict__ b_c,
    const float* __restrict__ eb_i, const float* __restrict__ eb_f,
    const float* __restrict__ eb_c,
    const float* __restrict__ e_ix, const float* __restrict__ e_ih,
    const float* __restrict__ e_fx, const float* __restrict__ e_fh,
    const float* __restrict__ e_cx, const float* __restrict__ e_ch,
    float* __restrict__ out)
{
    __shared__ float4 sx[II / 4];   // 2KB
    __shared__ float4 sh[HH / 4];   // 4KB
    __shared__ float4 scf[JT];

    const int tid = threadIdx.x;
    const int b   = blockIdx.y;
    const int j0  = blockIdx.x * JT;

    if (tid < 128) sx[tid] = ((const float4*)(x + b * II))[tid];
    sh[tid] = ((const float4*)(h_last + b * HH))[tid];

    if (tid < JT) {
        const int j   = j0 + tid;
        const int idx = b * HH + j;

        float pi = b_i[j], pf = b_f[j], po = b_o[j], pc = b_c[j];
#pragma unroll
        for (int c = 0; c < NKC; c++) {
            pi += g_part[c][0 * BH + idx];
            pf += g_part[c][1 * BH + idx];
            po += g_part[c][2 * BH + idx];
            pc += g_part[c][3 * BH + idx];
        }

        float i  = 1.f / (1.f + expf(-pi));
        float f  = 1.f / (1.f + expf(-pf));
        float o  = 1.f / (1.f + expf(-po));
        float ch = tanhf(pc);
        float cl = c_last[idx];

        float c = fmaf(f, cl, i * ch);
        float h = o * c;
        float di  = i * (1.f - i);
        float df  = f * (1.f - f);
        float dch = 1.f - ch * ch;
        float ai = di * ch;
        float af = df * cl;
        float ac = dch * i;

        out[OFF_H + idx]   = h;
        out[OFF_C + idx]   = c;
        out[OFF_EBI + idx] = fmaf(eb_i[idx], f, ai);
        out[OFF_EBF + idx] = fmaf(eb_f[idx], f, af);
        out[OFF_EBC + idx] = fmaf(eb_c[idx], f, ac);
        scf[tid] = make_float4(f, ai, af, ac);
    }
    __syncthreads();

    const size_t baseH = (size_t)(b * HH + j0) * (HH / 4);
    const size_t baseI = (size_t)(b * HH + j0) * (II / 4);

    const float4 hv = sh[tid];          // invariant across H-loop iterations
    const float4 xv = sx[tid & 127];    // invariant across X-loop iterations
    const int xsel = tid >> 7;          // 0/1: which scf pair in X loops

#define TRACE_H(SRC, OFF, SEL)                                              \
    {                                                                       \
        const float4* ein = (const float4*)(SRC) + baseH;                   \
        float4* eo = (float4*)(out + (OFF)) + baseH;                        \
        _Pragma("unroll")                                                   \
        for (int it = 0; it < JT; it++) {                                   \
            const int t = tid + it * 256;                                   \
            float4 cf = scf[it];                                            \
            float fv = cf.x, aa = cf.SEL;                                   \
            float4 e  = __ldcs(ein + t);                                    \
            float4 rr;                                                      \
            rr.x = fmaf(e.x, fv, aa * hv.x);                                \
            rr.y = fmaf(e.y, fv, aa * hv.y);                                \
            rr.z = fmaf(e.z, fv, aa * hv.z);                                \
            rr.w = fmaf(e.w, fv, aa * hv.w);                                \
            __stcs(eo + t, rr);                                             \
        }                                                                   \
    }

#define TRACE_X(SRC, OFF, SEL)                                              \
    {                                                                       \
        const float4* ein = (const float4*)(SRC) + baseI;                   \
        float4* eo = (float4*)(out + (OFF)) + baseI;                        \
        _Pragma("unroll")                                                   \
        for (int it = 0; it < JT / 2; it++) {                               \
            const int t = tid + it * 256;                                   \
            float4 cf = scf[it * 2 + xsel];                                 \
            float fv = cf.x, aa = cf.SEL;                                   \
            float4 e  = __ldcs(ein + t);                                    \
            float4 rr;                                                      \
            rr.x = fmaf(e.x, fv, aa * xv.x);                                \
            rr.y = fmaf(e.y, fv, aa * xv.y);                                \
            rr.z = fmaf(e.z, fv, aa * xv.z);                                \
            rr.w = fmaf(e.w, fv, aa * xv.w);                                \
            __stcs(eo + t, rr);                                             \
        }                                                                   \
    }

    TRACE_H(e_ih, OFF_EWIH, y)
    TRACE_H(e_fh, OFF_EWFH, z)
    TRACE_H(e_ch, OFF_EWCH, w)
    TRACE_X(e_ix, OFF_EWIX, y)
    TRACE_X(e_fx, OFF_EWFX, z)
    TRACE_X(e_cx, OFF_EWCX, w)
}

// ---------------------------------------------------------------------------
extern "C" void kernel_launch(void* const* d_in, const int* in_sizes, int n_in,
                              void* d_out, int out_size)
{
    const float* x      = (const float*)d_in[0];
    const float* w_ix   = (const float*)d_in[1];
    const float* w_ih   = (const float*)d_in[2];
    const float* b_i    = (const float*)d_in[3];
    const float* w_fx   = (const float*)d_in[4];
    const float* w_fh   = (const float*)d_in[5];
    const float* b_f    = (const float*)d_in[6];
    const float* w_ox   = (const float*)d_in[7];
    const float* w_oh   = (const float*)d_in[8];
    const float* b_o    = (const float*)d_in[9];
    const float* w_cx   = (const float*)d_in[10];
    const float* w_ch   = (const float*)d_in[11];
    const float* b_c    = (const float*)d_in[12];
    const float* h_last = (const float*)d_in[13];
    const float* c_last = (const float*)d_in[14];
    const float* e_w_ix = (const float*)d_in[15];
    const float* e_w_ih = (const float*)d_in[16];
    const float* e_b_i  = (const float*)d_in[17];
    const float* e_w_fx = (const float*)d_in[18];
    const float* e_w_fh = (const float*)d_in[19];
    const float* e_b_f  = (const float*)d_in[20];
    const float* e_w_cx = (const float*)d_in[21];
    const float* e_w_ch = (const float*)d_in[22];
    const float* e_b_c  = (const float*)d_in[23];
    float* out = (float*)d_out;

    GatePtrs p;
    p.wx[0] = w_ix; p.wx[1] = w_fx; p.wx[2] = w_ox; p.wx[3] = w_cx;
    p.wh[0] = w_ih; p.wh[1] = w_fh; p.wh[2] = w_oh; p.wh[3] = w_ch;

    dim3 g1(HH / 16, 4, NKC);
    gates_kernel<<<g1, 256>>>(x, h_last, p);

    dim3 g3(HH / JT, Bb);
    trace_kernel<<<g3, 256>>>(x, h_last, c_last, b_i, b_f, b_o, b_c,
                              e_b_i, e_b_f, e_b_c,
                              e_w_ix, e_w_ih, e_w_fx, e_w_fh,
                              e_w_cx, e_w_ch, out);
}